// round 6
// baseline (speedup 1.0000x reference)
#include <cuda_runtime.h>

#define FULLMASK 0xFFFFFFFFu
typedef unsigned long long u64;

__device__ float g_recon[8192];

// ---- f32x2 packed helpers ----
__device__ __forceinline__ u64 pk2(float lo, float hi) {
    u64 r; asm("mov.b64 %0, {%1, %2};" : "=l"(r) : "f"(lo), "f"(hi)); return r;
}
__device__ __forceinline__ void upk2(u64 v, float& lo, float& hi) {
    asm("mov.b64 {%0, %1}, %2;" : "=f"(lo), "=f"(hi) : "l"(v));
}
__device__ __forceinline__ u64 fma2(u64 a, u64 b, u64 c) {
    u64 d; asm("fma.rn.f32x2 %0, %1, %2, %3;" : "=l"(d) : "l"(a), "l"(b), "l"(c)); return d;
}
__device__ __forceinline__ u64 mul2(u64 a, u64 b) {
    u64 d; asm("mul.rn.f32x2 %0, %1, %2;" : "=l"(d) : "l"(a), "l"(b)); return d;
}

// Four batches per warp (8-lane segments). Lane sl (0..7) owns states 8sl+1..8sl+8.
// Linear space + power-of-two renorm every 8 steps. 5 shuffles/step serve 4 batches.
__global__ __launch_bounds__(128, 2)
void phmm_fwd_kernel(const int* __restrict__ x,
                     const float* __restrict__ a,
                     const float* __restrict__ e,
                     const float* __restrict__ mus,
                     const float* __restrict__ lvs,
                     int B, int E)
{
    const int warp  = (int)((blockIdx.x * blockDim.x + threadIdx.x) >> 5);
    const int lane  = threadIdx.x & 31;
    const int sl    = lane & 7;
    const int batch = 4 * warp + (lane >> 3);
    const int bc    = (batch < B) ? batch : (B - 1);   // clamp; final write guarded

    // ---- KLD for this segment's batch (hidden under startup latency) ----
    float kterm = 0.f;
    for (int j = sl; j < E; j += 8) {
        float m_ = mus[(size_t)bc * E + j];
        float v  = lvs[(size_t)bc * E + j];
        kterm += 1.f + v - m_ * m_ - __expf(v);
    }
    #pragma unroll
    for (int d = 4; d > 0; d >>= 1) kterm += __shfl_xor_sync(FULLMASK, kterm, d, 8);

    const float* ab  = a + (size_t)bc * 455;   // (65, 7)
    const float* ebp = e + (size_t)bc * 256;   // (64, 4)
    const int r0 = sl * 8;

    // enum: M2M=0, M2I=1, M2D=2, I2M=3, I2I=4, D2M=5, D2D=6
    float TMM[8], TIM[8], TDM[8], TMD[8], TDD[8], TMIs[8], TIIs[8];
    #pragma unroll
    for (int c = 0; c < 8; c++) {
        const float* rw = ab + (r0 + c) * 7;
        TMM[c] = __expf(rw[0]);
        TMD[c] = __expf(rw[2]);
        TIM[c] = __expf(rw[3]);
        TDM[c] = __expf(rw[5]);
        TDD[c] = __expf(rw[6]);
        const float* rwn = ab + (r0 + c + 1) * 7;   // own-state rows r0+1..r0+8
        TMIs[c] = 0.25f * __expf(rwn[1]);
        TIIs[c] = 0.25f * __expf(rwn[4]);
    }
    // predecessor-I recurrence coeffs (row 8sl); for sl==0 this tracks fI[0]
    float TMIqm = 0.25f * __expf(ab[r0 * 7 + 1]);
    float TIIqm = 0.25f * __expf(ab[r0 * 7 + 4]);
    // finals (used by sl==7)
    float TMMf = __expf(ab[64 * 7 + 0]);
    float TIMf = __expf(ab[64 * 7 + 3]);
    float TDMf = __expf(ab[64 * 7 + 5]);

    // boundary: fD[0] == 0 always -> zero its multipliers on segment lane 0
    if (sl == 0) { TDM[0] = 0.f; TDD[0] = 0.f; }

    u64 TMMp[4], TIMp[4], TDMp[4], TMIp[4], TIIp[4];
    #pragma unroll
    for (int p = 0; p < 4; p++) {
        TMMp[p] = pk2(TMM[2 * p], TMM[2 * p + 1]);
        TIMp[p] = pk2(TIM[2 * p], TIM[2 * p + 1]);
        TDMp[p] = pk2(TDM[2 * p], TDM[2 * p + 1]);
        TMIp[p] = pk2(TMIs[2 * p], TMIs[2 * p + 1]);
        TIIp[p] = pk2(TIIs[2 * p], TIIs[2 * p + 1]);
    }

    // emissions: own state 8sl+c uses e-row r0+c-1 -> rows r0..r0+7, pair-aligned
    u64 E0p[4], E1p[4], E2p[4], E3p[4];
    #pragma unroll
    for (int p = 0; p < 4; p++) {
        float4 ea = *reinterpret_cast<const float4*>(ebp + (r0 + 2 * p) * 4);
        float4 eb = *reinterpret_cast<const float4*>(ebp + (r0 + 2 * p + 1) * 4);
        E0p[p] = pk2(__expf(ea.x), __expf(eb.x));
        E1p[p] = pk2(__expf(ea.y), __expf(eb.y));
        E2p[p] = pk2(__expf(ea.z), __expf(eb.z));
        E3p[p] = pk2(__expf(ea.w), __expf(eb.w));
    }

    // Q prefixes: Q[c] = prod TDD[0..c-1] (time-invariant; 0 on sl==0)
    float Q[8];
    Q[1] = TDD[0];
    #pragma unroll
    for (int c = 2; c < 8; c++) Q[c] = Q[c - 1] * TDD[c - 1];
    float Rseg = Q[7] * TDD[7];

    // scan ratio prefixes over the 8-lane segment (zeroed below each level)
    float Rc = Rseg, Rp;
    float Rl1 = (sl >= 1) ? Rc : 0.f;
    Rp = __shfl_up_sync(FULLMASK, Rc, 1, 8); if (sl >= 1) Rc *= Rp;
    float Rl2 = (sl >= 2) ? Rc : 0.f;
    Rp = __shfl_up_sync(FULLMASK, Rc, 2, 8); if (sl >= 2) Rc *= Rp;
    float Rl4 = (sl >= 4) ? Rc : 0.f;

    // symbol packing: each lane holds the 16-symbol word for group sl
    unsigned word;
    {
        const int4* xv = reinterpret_cast<const int4*>(x + (size_t)bc * 128) + sl * 4;
        int4 q0 = xv[0], q1 = xv[1], q2 = xv[2], q3 = xv[3];
        word =  (unsigned)q0.x        | ((unsigned)q0.y << 2)  | ((unsigned)q0.z << 4)  | ((unsigned)q0.w << 6)
             | ((unsigned)q1.x << 8)  | ((unsigned)q1.y << 10) | ((unsigned)q1.z << 12) | ((unsigned)q1.w << 14)
             | ((unsigned)q2.x << 16) | ((unsigned)q2.y << 18) | ((unsigned)q2.z << 20) | ((unsigned)q2.w << 22)
             | ((unsigned)q3.x << 24) | ((unsigned)q3.y << 26) | ((unsigned)q3.z << 28) | ((unsigned)q3.w << 30);
    }

    // ---- state init + initial delete chain (only state 0 carries mass) ----
    u64 FMp[4] = {0ull, 0ull, 0ull, 0ull};
    u64 FIp[4] = {0ull, 0ull, 0ull, 0ull};
    float FD[8];                             // fD[8sl+0 .. 8sl+7]
    float FD8;                               // fD[8sl+8]
    float pFI = 0.f;                         // fI[8sl] (sl==0: fI[0])
    float pNprev = (sl == 0) ? 1.f : 0.f;    // fM[8sl] (t=0: fM0[0]=1)
    int expAcc = 0;
    {
        float P[9];
        P[1] = (sl == 0) ? TMD[0] : 0.f;     // A1 = TMD[0]*fM0[8sl]; A2..A8 = 0
        #pragma unroll
        for (int c = 2; c <= 8; c++) P[c] = TDD[c - 1] * P[c - 1];
        float Au = P[8], Ap;
        Ap = __shfl_up_sync(FULLMASK, Au, 1, 8); Au = fmaf(Rl1, Ap, Au);
        Ap = __shfl_up_sync(FULLMASK, Au, 2, 8); Au = fmaf(Rl2, Ap, Au);
        Ap = __shfl_up_sync(FULLMASK, Au, 4, 8); Au = fmaf(Rl4, Ap, Au);
        float Pex = __shfl_up_sync(FULLMASK, Au, 1, 8);
        FD[0] = Pex;                         // sl==0 garbage killed by TDM[0]=Q=0
        #pragma unroll
        for (int c = 1; c < 8; c++) FD[c] = fmaf(Q[c], Pex, P[c]);
        FD8 = Au;
    }

    // ---- main loop: 8 groups x 16 steps, renorm every 8 steps ----
    for (int w = 0; w < 8; w++) {
        unsigned pw = __shfl_sync(FULLMASK, word, w, 8);
        #pragma unroll
        for (int s = 0; s < 16; s++) {
            unsigned b1 = (pw >> (2 * s + 1)) & 1u;
            unsigned b0 = (pw >> (2 * s)) & 1u;

            u64 es[4];
            #pragma unroll
            for (int p = 0; p < 4; p++) {
                u64 lo = b0 ? E1p[p] : E0p[p];
                u64 hi = b0 ? E3p[p] : E2p[p];
                es[p] = b1 ? hi : lo;
            }

            // unpack state, build shifted predecessor pairs
            float fm[9], fi[9];
            fm[0] = pNprev; fi[0] = pFI;
            #pragma unroll
            for (int p = 0; p < 4; p++) {
                upk2(FMp[p], fm[2 * p + 1], fm[2 * p + 2]);
                upk2(FIp[p], fi[2 * p + 1], fi[2 * p + 2]);
            }

            u64 nM[4], nI[4];
            #pragma unroll
            for (int p = 0; p < 4; p++) {
                u64 pM = pk2(fm[2 * p], fm[2 * p + 1]);
                u64 pI = pk2(fi[2 * p], fi[2 * p + 1]);
                u64 pD = pk2(FD[2 * p], FD[2 * p + 1]);
                u64 t  = fma2(TMMp[p], pM, fma2(TIMp[p], pI, mul2(TDMp[p], pD)));
                nM[p]  = mul2(es[p], t);
                nI[p]  = fma2(TMIp[p], FMp[p], mul2(TIIp[p], FIp[p]));
            }
            float npFI = fmaf(TMIqm, pNprev, TIIqm * pFI);

            // delete chain on NEW fM
            float nfm[9];
            #pragma unroll
            for (int p = 0; p < 4; p++) upk2(nM[p], nfm[2 * p + 1], nfm[2 * p + 2]);
            float pN = __shfl_up_sync(FULLMASK, nfm[8], 1, 8);
            if (sl == 0) pN = 0.f;           // fM_new[0] = 0 for l >= 1
            nfm[0] = pN;

            float P[9];
            P[1] = TMD[0] * pN;
            #pragma unroll
            for (int c = 2; c <= 8; c++)
                P[c] = fmaf(TDD[c - 1], P[c - 1], TMD[c - 1] * nfm[c - 1]);
            float Au = P[8], Ap;
            Ap = __shfl_up_sync(FULLMASK, Au, 1, 8); Au = fmaf(Rl1, Ap, Au);
            Ap = __shfl_up_sync(FULLMASK, Au, 2, 8); Au = fmaf(Rl2, Ap, Au);
            Ap = __shfl_up_sync(FULLMASK, Au, 4, 8); Au = fmaf(Rl4, Ap, Au);
            float Pex = __shfl_up_sync(FULLMASK, Au, 1, 8);
            FD[0] = Pex;
            #pragma unroll
            for (int c = 1; c < 8; c++) FD[c] = fmaf(Q[c], Pex, P[c]);
            FD8 = Au;

            pNprev = pN; pFI = npFI;
            #pragma unroll
            for (int p = 0; p < 4; p++) { FMp[p] = nM[p]; FIp[p] = nI[p]; }

            if (s == 7 || s == 15) {   // renorm every 8 steps
                float m = fmaxf(pFI, FD8);
                #pragma unroll
                for (int c = 1; c <= 8; c++) m = fmaxf(m, nfm[c]);
                #pragma unroll
                for (int c = 1; c < 8; c++) m = fmaxf(m, FD[c]);
                float ia, ib;
                #pragma unroll
                for (int p = 0; p < 4; p++) {
                    upk2(FIp[p], ia, ib);
                    m = fmaxf(m, fmaxf(ia, ib));
                }
                #pragma unroll
                for (int d = 4; d > 0; d >>= 1)
                    m = fmaxf(m, __shfl_xor_sync(FULLMASK, m, d, 8));
                int eb = (__float_as_int(m) >> 23) & 255;
                eb = max(1, min(253, eb));
                float sc = __int_as_float((254 - eb) << 23);  // 2^(127-eb)
                expAcc += eb - 127;
                u64 sp = pk2(sc, sc);
                #pragma unroll
                for (int p = 0; p < 4; p++) {
                    FMp[p] = mul2(FMp[p], sp);
                    FIp[p] = mul2(FIp[p], sp);
                }
                #pragma unroll
                for (int c = 0; c < 8; c++) FD[c] *= sc;
                FD8 *= sc; pFI *= sc; pNprev *= sc;
            }
        }
    }

    if (sl == 7 && batch < B) {
        float d_, FM8, FI8;
        upk2(FMp[3], d_, FM8);
        upk2(FIp[3], d_, FI8);
        float S = fmaf(TMMf, FM8, fmaf(TIMf, FI8, TDMf * FD8));
        S = fmaxf(S, 1e-37f);
        g_recon[batch] = -(logf(S) + (float)expAcc * 0.69314718055994530942f)
                         - 0.5f * kterm;
    }
}

// deterministic mean of g_recon[0..B): one block, float4 loads, fixed order
__global__ void reduce_kernel(float* __restrict__ out, int B)
{
    int t = threadIdx.x;                         // 1024 threads
    const float4* g4 = reinterpret_cast<const float4*>(g_recon);
    int n4 = B >> 2;
    float s = 0.f;
    for (int i = t; i < n4; i += 1024) {
        float4 v = g4[i];
        s += (v.x + v.y) + (v.z + v.w);
    }
    #pragma unroll
    for (int d = 16; d > 0; d >>= 1) s += __shfl_xor_sync(FULLMASK, s, d);
    __shared__ float sh[32];
    if ((t & 31) == 0) sh[t >> 5] = s;
    __syncthreads();
    if (t < 32) {
        float v = sh[t];
        #pragma unroll
        for (int d = 16; d > 0; d >>= 1) v += __shfl_xor_sync(FULLMASK, v, d);
        if (t == 0) out[0] = v / (float)B;
    }
}

extern "C" void kernel_launch(void* const* d_in, const int* in_sizes, int n_in,
                              void* d_out, int out_size)
{
    const int*   x   = (const int*)d_in[0];     // (B, 128) int32
    const float* a   = (const float*)d_in[1];   // (B, 65, 7)
    const float* e   = (const float*)d_in[2];   // (B, 64, 4)
    const float* mus = (const float*)d_in[3];   // (B, E)
    const float* lvs = (const float*)d_in[4];   // (B, E)

    int B = in_sizes[1] / 455;                  // (K+1)*7 = 455
    if (B > 8192) B = 8192;
    int E = in_sizes[3] / B;

    int blocks = (B + 15) / 16;                 // 16 batches per 128-thread block
    phmm_fwd_kernel<<<blocks, 128>>>(x, a, e, mus, lvs, B, E);
    reduce_kernel<<<1, 1024>>>((float*)d_out, B);
}

// round 8
// speedup vs baseline: 1.2786x; 1.2786x over previous
#include <cuda_runtime.h>

#define FULLMASK 0xFFFFFFFFu
typedef unsigned long long u64;

__device__ float g_recon[8192];
__device__ unsigned g_count = 0;

// ---- f32x2 packed helpers ----
__device__ __forceinline__ u64 pk2(float lo, float hi) {
    u64 r; asm("mov.b64 %0, {%1, %2};" : "=l"(r) : "f"(lo), "f"(hi)); return r;
}
__device__ __forceinline__ void upk2(u64 v, float& lo, float& hi) {
    asm("mov.b64 {%0, %1}, %2;" : "=f"(lo), "=f"(hi) : "l"(v));
}
__device__ __forceinline__ u64 fma2(u64 a, u64 b, u64 c) {
    u64 d; asm("fma.rn.f32x2 %0, %1, %2, %3;" : "=l"(d) : "l"(a), "l"(b), "l"(c)); return d;
}
__device__ __forceinline__ u64 mul2(u64 a, u64 b) {
    u64 d; asm("mul.rn.f32x2 %0, %1, %2;" : "=l"(d) : "l"(a), "l"(b)); return d;
}

// Two batches per warp (16-lane segments). Lane sl (0..15) owns states 4sl+1..4sl+4.
// Linear space + power-of-two renorm every 8 steps. KLD folded into load phase.
// Final mean fused via deterministic last-block tailgate.
__global__ __launch_bounds__(128, 4)
void phmm_fused_kernel(const int* __restrict__ x,
                       const float* __restrict__ a,
                       const float* __restrict__ e,
                       const float* __restrict__ mus,
                       const float* __restrict__ lvs,
                       float* __restrict__ out, int B, int E)
{
    const int warp  = (int)((blockIdx.x * blockDim.x + threadIdx.x) >> 5);
    const int lane  = threadIdx.x & 31;
    const int sl    = lane & 15;
    const int batch = 2 * warp + (lane >> 4);
    const int bc    = (batch < B) ? batch : (B - 1);   // clamp; final write guarded

    // ---- KLD for this segment's batch (hidden under startup latency) ----
    float kterm = 0.f;
    if (sl < E) {
        float m_ = mus[(size_t)bc * E + sl];
        float v  = lvs[(size_t)bc * E + sl];
        kterm = 1.f + v - m_ * m_ - __expf(v);
    }
    #pragma unroll
    for (int d = 8; d > 0; d >>= 1) kterm += __shfl_xor_sync(FULLMASK, kterm, d, 16);

    const float* ab  = a + (size_t)bc * 455;   // (65, 7)
    const float* ebp = e + (size_t)bc * 256;   // (64, 4)
    const int r0 = sl * 4;

    // enum: M2M=0, M2I=1, M2D=2, I2M=3, I2I=4, D2M=5, D2D=6
    float TMM[4], TIM[4], TDM[4], TMD[4], TDD[4], TMIq[4], TIIq[4];
    #pragma unroll
    for (int c = 0; c < 4; c++) {
        const float* rw = ab + (r0 + c) * 7;
        TMM[c] = __expf(rw[0]);
        TMD[c] = __expf(rw[2]);
        TIM[c] = __expf(rw[3]);
        TDM[c] = __expf(rw[5]);
        TDD[c] = __expf(rw[6]);
        const float* rwn = ab + (r0 + c + 1) * 7;
        TMIq[c] = 0.25f * __expf(rwn[1]);
        TIIq[c] = 0.25f * __expf(rwn[4]);
    }
    // predecessor-I recurrence coeffs (row 4sl); for sl==0 this tracks fI[0]
    float TMIqm = 0.25f * __expf(ab[r0 * 7 + 1]);
    float TIIqm = 0.25f * __expf(ab[r0 * 7 + 4]);
    // finals (used by sl==15)
    float TMMf = __expf(ab[64 * 7 + 0]);
    float TIMf = __expf(ab[64 * 7 + 3]);
    float TDMf = __expf(ab[64 * 7 + 5]);

    // boundary: fD[0] == 0 always -> zero its multipliers on segment lane 0
    if (sl == 0) { TDM[0] = 0.f; TDD[0] = 0.f; }

    u64 TMM01 = pk2(TMM[0], TMM[1]), TMM23 = pk2(TMM[2], TMM[3]);
    u64 TIM01 = pk2(TIM[0], TIM[1]), TIM23 = pk2(TIM[2], TIM[3]);
    u64 TDM01 = pk2(TDM[0], TDM[1]), TDM23 = pk2(TDM[2], TDM[3]);
    u64 TMI01 = pk2(TMIq[0], TMIq[1]), TMI23 = pk2(TMIq[2], TMIq[3]);
    u64 TII01 = pk2(TIIq[0], TIIq[1]), TII23 = pk2(TIIq[2], TIIq[3]);

    // emissions: state 4sl+1+c uses e row r0+c
    float4 er0 = *reinterpret_cast<const float4*>(ebp + (r0 + 0) * 4);
    float4 er1 = *reinterpret_cast<const float4*>(ebp + (r0 + 1) * 4);
    float4 er2 = *reinterpret_cast<const float4*>(ebp + (r0 + 2) * 4);
    float4 er3 = *reinterpret_cast<const float4*>(ebp + (r0 + 3) * 4);
    u64 E0_01 = pk2(__expf(er0.x), __expf(er1.x)), E0_23 = pk2(__expf(er2.x), __expf(er3.x));
    u64 E1_01 = pk2(__expf(er0.y), __expf(er1.y)), E1_23 = pk2(__expf(er2.y), __expf(er3.y));
    u64 E2_01 = pk2(__expf(er0.z), __expf(er1.z)), E2_23 = pk2(__expf(er2.z), __expf(er3.z));
    u64 E3_01 = pk2(__expf(er0.w), __expf(er1.w)), E3_23 = pk2(__expf(er2.w), __expf(er3.w));

    // scan ratio prefixes over the 16-lane segment (zeroed below each level)
    float Rc = TDD[3] * TDD[2] * TDD[1] * TDD[0], Rp;
    float Rl1 = (sl >= 1) ? Rc : 0.f;
    Rp = __shfl_up_sync(FULLMASK, Rc, 1, 16); if (sl >= 1) Rc *= Rp;
    float Rl2 = (sl >= 2) ? Rc : 0.f;
    Rp = __shfl_up_sync(FULLMASK, Rc, 2, 16); if (sl >= 2) Rc *= Rp;
    float Rl4 = (sl >= 4) ? Rc : 0.f;
    Rp = __shfl_up_sync(FULLMASK, Rc, 4, 16); if (sl >= 4) Rc *= Rp;
    float Rl8 = (sl >= 8) ? Rc : 0.f;

    // symbol packing: lanes sl<8 hold the 16-symbol word for group sl
    unsigned word = 0;
    if (sl < 8) {
        const int4* xv = reinterpret_cast<const int4*>(x + (size_t)bc * 128) + sl * 4;
        int4 q0 = xv[0], q1 = xv[1], q2 = xv[2], q3 = xv[3];
        word =  (unsigned)q0.x        | ((unsigned)q0.y << 2)  | ((unsigned)q0.z << 4)  | ((unsigned)q0.w << 6)
             | ((unsigned)q1.x << 8)  | ((unsigned)q1.y << 10) | ((unsigned)q1.z << 12) | ((unsigned)q1.w << 14)
             | ((unsigned)q2.x << 16) | ((unsigned)q2.y << 18) | ((unsigned)q2.z << 20) | ((unsigned)q2.w << 22)
             | ((unsigned)q3.x << 24) | ((unsigned)q3.y << 26) | ((unsigned)q3.z << 28) | ((unsigned)q3.w << 30);
    }

    // ---- state init + initial delete chain (only state 0 carries mass) ----
    u64 FMp01 = 0ull, FMp23 = 0ull, FIp01 = 0ull, FIp23 = 0ull;
    float FD1, FD2, FD3, FD4;
    float pFI = 0.f;                         // fI[4sl] (sl==0: fI[0])
    float pNprev = (sl == 0) ? 1.f : 0.f;    // fM[4sl] (t=0: fM0[0]=1)
    float Pexprev;                           // fD[4sl]
    int expAcc = 0;
    {
        float A1 = (sl == 0) ? TMD[0] : 0.f; // A2=A3=A4=0
        float Au = TDD[3] * (TDD[2] * (TDD[1] * A1)), Ap;
        Ap = __shfl_up_sync(FULLMASK, Au, 1, 16); Au = fmaf(Rl1, Ap, Au);
        Ap = __shfl_up_sync(FULLMASK, Au, 2, 16); Au = fmaf(Rl2, Ap, Au);
        Ap = __shfl_up_sync(FULLMASK, Au, 4, 16); Au = fmaf(Rl4, Ap, Au);
        Ap = __shfl_up_sync(FULLMASK, Au, 8, 16); Au = fmaf(Rl8, Ap, Au);
        float Pex = __shfl_up_sync(FULLMASK, Au, 1, 16);
        FD1 = fmaf(TDD[0], Pex, A1);         // TDD[0]=0 on sl==0 -> Pex garbage ok
        FD2 = TDD[1] * FD1;
        FD3 = TDD[2] * FD2;
        FD4 = Au;
        Pexprev = Pex;                       // sl==0 garbage killed by TDM[0]=0
    }

    // ---- main loop: 8 groups x 16 steps, renorm every 8 steps ----
    for (int w = 0; w < 8; w++) {
        unsigned pw = __shfl_sync(FULLMASK, word, w, 16);
        #pragma unroll
        for (int s = 0; s < 16; s++) {
            unsigned b1 = (pw >> (2 * s + 1)) & 1u;
            unsigned b0 = (pw >> (2 * s)) & 1u;
            u64 es01 = b1 ? (b0 ? E3_01 : E2_01) : (b0 ? E1_01 : E0_01);
            u64 es23 = b1 ? (b0 ? E3_23 : E2_23) : (b0 ? E1_23 : E0_23);

            float FM1, FM2, FM3, FM4, FI1, FI2, FI3, FI4;
            upk2(FMp01, FM1, FM2); upk2(FMp23, FM3, FM4);
            upk2(FIp01, FI1, FI2); upk2(FIp23, FI3, FI4);

            u64 prevM01 = pk2(pNprev, FM1),  prevM23 = pk2(FM2, FM3);
            u64 prevI01 = pk2(pFI, FI1),     prevI23 = pk2(FI2, FI3);
            u64 prevD01 = pk2(Pexprev, FD1), prevD23 = pk2(FD2, FD3);

            u64 t01 = fma2(TMM01, prevM01, fma2(TIM01, prevI01, mul2(TDM01, prevD01)));
            u64 t23 = fma2(TMM23, prevM23, fma2(TIM23, prevI23, mul2(TDM23, prevD23)));
            u64 nM01 = mul2(es01, t01), nM23 = mul2(es23, t23);
            float nFM1, nFM2, nFM3, nFM4;
            upk2(nM01, nFM1, nFM2); upk2(nM23, nFM3, nFM4);

            // insert states (own rows) + predecessor-I local recurrence
            u64 nI01 = fma2(TMI01, FMp01, mul2(TII01, FIp01));
            u64 nI23 = fma2(TMI23, FMp23, mul2(TII23, FIp23));
            pFI = fmaf(TMIqm, pNprev, TIIqm * pFI);

            // delete chain on NEW fM (4-level segment scan)
            float pN = __shfl_up_sync(FULLMASK, nFM4, 1, 16);
            if (sl == 0) pN = 0.f;           // fM_new[0] = 0 for l >= 1
            float A1 = TMD[0] * pN, A2 = TMD[1] * nFM1;
            float A3 = TMD[2] * nFM2, A4 = TMD[3] * nFM3;
            float Au = fmaf(TDD[3], fmaf(TDD[2], fmaf(TDD[1], A1, A2), A3), A4);
            float Ap;
            Ap = __shfl_up_sync(FULLMASK, Au, 1, 16); Au = fmaf(Rl1, Ap, Au);
            Ap = __shfl_up_sync(FULLMASK, Au, 2, 16); Au = fmaf(Rl2, Ap, Au);
            Ap = __shfl_up_sync(FULLMASK, Au, 4, 16); Au = fmaf(Rl4, Ap, Au);
            Ap = __shfl_up_sync(FULLMASK, Au, 8, 16); Au = fmaf(Rl8, Ap, Au);
            float Pex = __shfl_up_sync(FULLMASK, Au, 1, 16);
            FD1 = fmaf(TDD[0], Pex, A1);
            FD2 = fmaf(TDD[1], FD1, A2);
            FD3 = fmaf(TDD[2], FD2, A3);
            FD4 = Au;

            pNprev = pN; Pexprev = Pex;
            FMp01 = nM01; FMp23 = nM23;
            FIp01 = nI01; FIp23 = nI23;

            if (s == 7 || s == 15) {   // renorm every 8 steps
                float m1, m2, m3, m4, i1, i2, i3, i4;
                upk2(FMp01, m1, m2); upk2(FMp23, m3, m4);
                upk2(FIp01, i1, i2); upk2(FIp23, i3, i4);
                float m = fmaxf(fmaxf(fmaxf(m1, m2), fmaxf(m3, m4)),
                                fmaxf(fmaxf(i1, i2), fmaxf(i3, i4)));
                m = fmaxf(m, fmaxf(fmaxf(FD1, FD2), fmaxf(FD3, FD4)));
                m = fmaxf(m, pFI);
                #pragma unroll
                for (int d = 8; d > 0; d >>= 1)
                    m = fmaxf(m, __shfl_xor_sync(FULLMASK, m, d, 16));
                int eb = (__float_as_int(m) >> 23) & 255;
                eb = max(1, min(253, eb));
                float sc = __int_as_float((254 - eb) << 23);  // 2^(127-eb)
                expAcc += eb - 127;
                u64 sp = pk2(sc, sc);
                FMp01 = mul2(FMp01, sp); FMp23 = mul2(FMp23, sp);
                FIp01 = mul2(FIp01, sp); FIp23 = mul2(FIp23, sp);
                FD1 *= sc; FD2 *= sc; FD3 *= sc; FD4 *= sc;
                pFI *= sc; pNprev *= sc; Pexprev *= sc;
            }
        }
    }

    if (sl == 15 && batch < B) {
        float FM4, FI4, d_;
        upk2(FMp23, d_, FM4);
        upk2(FIp23, d_, FI4);
        float S = fmaf(TMMf, FM4, fmaf(TIMf, FI4, TDMf * FD4));
        S = fmaxf(S, 1e-37f);
        g_recon[batch] = -(logf(S) + (float)expAcc * 0.69314718055994530942f)
                         - 0.5f * kterm;
    }

    // ---- deterministic fused final reduction (classic threadfence pattern) ----
    __syncthreads();                      // order this block's g_recon stores
    __shared__ unsigned sIsLast;
    if (threadIdx.x == 0) {
        __threadfence();                  // release: publish g_recon writes
        unsigned v = atomicAdd(&g_count, 1u);
        sIsLast = (v == gridDim.x - 1) ? 1u : 0u;
    }
    __syncthreads();
    if (sIsLast) {
        __threadfence();                  // acquire: see all g_recon writes
        int t = threadIdx.x;              // 128 threads
        const float4* g4 = reinterpret_cast<const float4*>(g_recon);
        int n4 = B >> 2;
        float ssum = 0.f;
        for (int i = t; i < n4; i += 128) {
            float4 v = g4[i];
            ssum += (v.x + v.y) + (v.z + v.w);
        }
        #pragma unroll
        for (int d = 16; d > 0; d >>= 1)
            ssum += __shfl_xor_sync(FULLMASK, ssum, d);
        __shared__ float sh[4];
        if ((t & 31) == 0) sh[t >> 5] = ssum;
        __syncthreads();
        if (t == 0) {
            out[0] = (sh[0] + sh[1] + sh[2] + sh[3]) / (float)B;
            g_count = 0;                  // reset for next graph replay
        }
    }
}

extern "C" void kernel_launch(void* const* d_in, const int* in_sizes, int n_in,
                              void* d_out, int out_size)
{
    const int*   x   = (const int*)d_in[0];     // (B, 128) int32
    const float* a   = (const float*)d_in[1];   // (B, 65, 7)
    const float* e   = (const float*)d_in[2];   // (B, 64, 4)
    const float* mus = (const float*)d_in[3];   // (B, E)
    const float* lvs = (const float*)d_in[4];   // (B, E)

    int B = in_sizes[1] / 455;                  // (K+1)*7 = 455
    if (B > 8192) B = 8192;
    int E = in_sizes[3] / B;

    int blocks = (B + 7) / 8;                   // 8 batches per 128-thread block
    phmm_fused_kernel<<<blocks, 128>>>(x, a, e, mus, lvs, (float*)d_out, B, E);
}

// round 9
// speedup vs baseline: 1.4090x; 1.1020x over previous
#include <cuda_runtime.h>

#define FULLMASK 0xFFFFFFFFu

__device__ float g_recon[8192];
__device__ unsigned g_count = 0;

// Four batches per warp (8-lane segments). Lane sl (0..7) owns states 8sl+1..8sl+8.
// Fully scalar updates (state shift = register renaming). Emissions in per-thread
// private SMEM slots. Linear space + power-of-two renorm every 8 steps.
// Fused KLD + deterministic last-block-tailgate mean.
__global__ __launch_bounds__(128, 2)
void phmm_fused_kernel(const int* __restrict__ x,
                       const float* __restrict__ a,
                       const float* __restrict__ e,
                       const float* __restrict__ mus,
                       const float* __restrict__ lvs,
                       float* __restrict__ out, int B, int E)
{
    __shared__ float es_sm[128 * 36];   // [tid][sym][8 rows], stride 36 words

    const int tid   = threadIdx.x;
    const int warp  = (int)((blockIdx.x * blockDim.x + tid) >> 5);
    const int lane  = tid & 31;
    const int sl    = lane & 7;
    const int batch = 4 * warp + (lane >> 3);
    const int bc    = (batch < B) ? batch : (B - 1);   // clamp; final write guarded

    // ---- KLD for this segment's batch ----
    float kterm = 0.f;
    for (int j = sl; j < E; j += 8) {
        float m_ = mus[(size_t)bc * E + j];
        float v  = lvs[(size_t)bc * E + j];
        kterm += 1.f + v - m_ * m_ - __expf(v);
    }
    #pragma unroll
    for (int d = 4; d > 0; d >>= 1) kterm += __shfl_xor_sync(FULLMASK, kterm, d, 8);

    const float* ab  = a + (size_t)bc * 455;   // (65, 7)
    const float* ebp = e + (size_t)bc * 256;   // (64, 4)
    const int r0 = sl * 8;

    // enum: M2M=0, M2I=1, M2D=2, I2M=3, I2I=4, D2M=5, D2D=6
    float TMM[8], TIM[8], TDM[8], TMD[8], TDD[8], TMIq[8], TIIq[8];
    #pragma unroll
    for (int c = 0; c < 8; c++) {
        const float* rw = ab + (r0 + c) * 7;
        TMM[c]  = __expf(rw[0]);
        TMIq[c] = 0.25f * __expf(rw[1]);
        TMD[c]  = __expf(rw[2]);
        TIM[c]  = __expf(rw[3]);
        TIIq[c] = 0.25f * __expf(rw[4]);
        TDM[c]  = __expf(rw[5]);
        TDD[c]  = __expf(rw[6]);
    }
    // row r0+8 insert coeffs (tracks fI at segment end; lane7: fI[64])
    float TMI8 = 0.25f * __expf(ab[(r0 + 8) * 7 + 1]);
    float TII8 = 0.25f * __expf(ab[(r0 + 8) * 7 + 4]);
    // finals (used by sl==7)
    float TMMf = __expf(ab[64 * 7 + 0]);
    float TIMf = __expf(ab[64 * 7 + 3]);
    float TDMf = __expf(ab[64 * 7 + 5]);

    // ---- emissions -> private SMEM slots: es_sm[tid*36 + sym*8 + c] ----
    {
        float* myes = es_sm + tid * 36;
        #pragma unroll
        for (int c = 0; c < 8; c++) {
            float4 er = *reinterpret_cast<const float4*>(ebp + (r0 + c) * 4);
            myes[0 * 8 + c] = __expf(er.x);
            myes[1 * 8 + c] = __expf(er.y);
            myes[2 * 8 + c] = __expf(er.z);
            myes[3 * 8 + c] = __expf(er.w);
        }
    }
    // slots are thread-private: no block sync needed

    // Q prefixes: Q[c] = prod TDD[0..c-1] (time-invariant)
    float Q[8];
    Q[1] = TDD[0];
    #pragma unroll
    for (int c = 2; c < 8; c++) Q[c] = Q[c - 1] * TDD[c - 1];
    float Rseg = Q[7] * TDD[7];

    // scan ratio prefixes over the 8-lane segment (zeroed below each level)
    float Rc = Rseg, Rp;
    float Rl1 = (sl >= 1) ? Rc : 0.f;
    Rp = __shfl_up_sync(FULLMASK, Rc, 1, 8); if (sl >= 1) Rc *= Rp;
    float Rl2 = (sl >= 2) ? Rc : 0.f;
    Rp = __shfl_up_sync(FULLMASK, Rc, 2, 8); if (sl >= 2) Rc *= Rp;
    float Rl4 = (sl >= 4) ? Rc : 0.f;

    // symbol packing: lane sl holds the 16-symbol word for time group sl
    unsigned word;
    {
        const int4* xv = reinterpret_cast<const int4*>(x + (size_t)bc * 128) + sl * 4;
        int4 q0 = xv[0], q1 = xv[1], q2 = xv[2], q3 = xv[3];
        word =  (unsigned)q0.x        | ((unsigned)q0.y << 2)  | ((unsigned)q0.z << 4)  | ((unsigned)q0.w << 6)
             | ((unsigned)q1.x << 8)  | ((unsigned)q1.y << 10) | ((unsigned)q1.z << 12) | ((unsigned)q1.w << 14)
             | ((unsigned)q2.x << 16) | ((unsigned)q2.y << 18) | ((unsigned)q2.z << 20) | ((unsigned)q2.w << 22)
             | ((unsigned)q3.x << 24) | ((unsigned)q3.y << 26) | ((unsigned)q3.z << 28) | ((unsigned)q3.w << 30);
    }

    // ---- state: fMo[c]=fM[8sl+c] c=0..7; fI[c]=fI[8sl+c]; fD[c]=fD[8sl+c]; +seg-end extras
    float fMo[8], fI[8], fD[8];
    float fM8 = 0.f, fI8 = 0.f, FD8;
    #pragma unroll
    for (int c = 0; c < 8; c++) { fMo[c] = 0.f; fI[c] = 0.f; }
    fMo[0] = (sl == 0) ? 1.f : 0.f;          // fM0[0] = 1 (linear)
    int expAcc = 0;

    // initial delete chain (only state 0 carries mass)
    {
        float u[9];
        u[1] = TMD[0] * fMo[0];
        #pragma unroll
        for (int c = 2; c <= 8; c++) u[c] = TDD[c - 1] * u[c - 1];
        float Au = u[8], Ap;
        Ap = __shfl_up_sync(FULLMASK, Au, 1, 8); Au = fmaf(Rl1, Ap, Au);
        Ap = __shfl_up_sync(FULLMASK, Au, 2, 8); Au = fmaf(Rl2, Ap, Au);
        Ap = __shfl_up_sync(FULLMASK, Au, 4, 8); Au = fmaf(Rl4, Ap, Au);
        float Pex = __shfl_up_sync(FULLMASK, Au, 1, 8);
        if (sl == 0) Pex = 0.f;
        fD[0] = Pex;
        #pragma unroll
        for (int c = 1; c < 8; c++) fD[c] = fmaf(Q[c], Pex, u[c]);
        FD8 = Au;
    }

    const float* myes = es_sm + tid * 36;

    // ---- main loop: 8 groups x 16 steps, renorm every 8 steps ----
    for (int w = 0; w < 8; w++) {
        unsigned pw = __shfl_sync(FULLMASK, word, w, 8);
        #pragma unroll
        for (int s = 0; s < 16; s++) {
            int sym = (int)((pw >> (2 * s)) & 3u);
            const float4* ep = reinterpret_cast<const float4*>(myes + sym * 8);
            float4 eA = ep[0], eB = ep[1];
            float es_[8] = {eA.x, eA.y, eA.z, eA.w, eB.x, eB.y, eB.z, eB.w};

            // M update: nf[c+1] = es_c * (TMM*fM + TIM*fI + TDM*fD) at row c
            float nf[9];
            #pragma unroll
            for (int c = 0; c < 8; c++)
                nf[c + 1] = es_[c] * fmaf(TMM[c], fMo[c],
                                    fmaf(TIM[c], fI[c], TDM[c] * fD[c]));

            // I update (own rows, in place; uses OLD fM)
            #pragma unroll
            for (int c = 0; c < 8; c++)
                fI[c] = fmaf(TMIq[c], fMo[c], TIIq[c] * fI[c]);
            fI8 = fmaf(TMI8, fM8, TII8 * fI8);
            fM8 = nf[8];

            // delete chain on NEW fM
            float pN = __shfl_up_sync(FULLMASK, nf[8], 1, 8);
            if (sl == 0) pN = 0.f;           // fM_new[0] = 0 for l >= 1
            float u[9];
            u[1] = TMD[0] * pN;
            #pragma unroll
            for (int c = 2; c <= 8; c++)
                u[c] = fmaf(TDD[c - 1], u[c - 1], TMD[c - 1] * nf[c - 1]);
            float Au = u[8], Ap;
            Ap = __shfl_up_sync(FULLMASK, Au, 1, 8); Au = fmaf(Rl1, Ap, Au);
            Ap = __shfl_up_sync(FULLMASK, Au, 2, 8); Au = fmaf(Rl2, Ap, Au);
            Ap = __shfl_up_sync(FULLMASK, Au, 4, 8); Au = fmaf(Rl4, Ap, Au);
            float Pex = __shfl_up_sync(FULLMASK, Au, 1, 8);
            if (sl == 0) Pex = 0.f;
            fD[0] = Pex;
            #pragma unroll
            for (int c = 1; c < 8; c++) fD[c] = fmaf(Q[c], Pex, u[c]);
            FD8 = Au;

            // rotate M state (pure renaming)
            fMo[0] = pN;
            #pragma unroll
            for (int c = 1; c < 8; c++) fMo[c] = nf[c];

            if (s == 7 || s == 15) {   // renorm every 8 steps
                float m = fmaxf(fI8, FD8);
                #pragma unroll
                for (int c = 0; c < 8; c++) {
                    m = fmaxf(m, fMo[c]);
                    m = fmaxf(m, fI[c]);
                    m = fmaxf(m, fD[c]);
                }
                m = fmaxf(m, fM8);
                #pragma unroll
                for (int d = 4; d > 0; d >>= 1)
                    m = fmaxf(m, __shfl_xor_sync(FULLMASK, m, d, 8));
                int eb = (__float_as_int(m) >> 23) & 255;
                eb = max(1, min(253, eb));
                float sc = __int_as_float((254 - eb) << 23);  // 2^(127-eb)
                expAcc += eb - 127;
                #pragma unroll
                for (int c = 0; c < 8; c++) {
                    fMo[c] *= sc; fI[c] *= sc; fD[c] *= sc;
                }
                fM8 *= sc; fI8 *= sc; FD8 *= sc;
            }
        }
    }

    if (sl == 7 && batch < B) {
        float S = fmaf(TMMf, fM8, fmaf(TIMf, fI8, TDMf * FD8));
        S = fmaxf(S, 1e-37f);
        g_recon[batch] = -(logf(S) + (float)expAcc * 0.69314718055994530942f)
                         - 0.5f * kterm;
    }

    // ---- deterministic fused final reduction (threadfence tailgate) ----
    __syncthreads();                      // order this block's g_recon stores
    __shared__ unsigned sIsLast;
    if (tid == 0) {
        __threadfence();                  // release: publish g_recon writes
        unsigned v = atomicAdd(&g_count, 1u);
        sIsLast = (v == gridDim.x - 1) ? 1u : 0u;
    }
    __syncthreads();
    if (sIsLast) {
        __threadfence();                  // acquire: see all g_recon writes
        const float4* g4 = reinterpret_cast<const float4*>(g_recon);
        int n4 = B >> 2;                  // 1024 for B=4096
        // MLP-8 independent partials, fixed summation order per thread
        float p[8];
        #pragma unroll
        for (int k = 0; k < 8; k++) p[k] = 0.f;
        for (int i0 = tid; i0 < n4; i0 += 128 * 8) {
            #pragma unroll
            for (int k = 0; k < 8; k++) {
                int i = i0 + k * 128;
                if (i < n4) {
                    float4 v = g4[i];
                    p[k] += (v.x + v.y) + (v.z + v.w);
                }
            }
        }
        float ssum = ((p[0] + p[1]) + (p[2] + p[3])) + ((p[4] + p[5]) + (p[6] + p[7]));
        #pragma unroll
        for (int d = 16; d > 0; d >>= 1)
            ssum += __shfl_xor_sync(FULLMASK, ssum, d);
        __shared__ float sh[4];
        if ((tid & 31) == 0) sh[tid >> 5] = ssum;
        __syncthreads();
        if (tid == 0) {
            out[0] = (sh[0] + sh[1] + sh[2] + sh[3]) / (float)B;
            g_count = 0;                  // reset for next graph replay
        }
    }
}

extern "C" void kernel_launch(void* const* d_in, const int* in_sizes, int n_in,
                              void* d_out, int out_size)
{
    const int*   x   = (const int*)d_in[0];     // (B, 128) int32
    const float* a   = (const float*)d_in[1];   // (B, 65, 7)
    const float* e   = (const float*)d_in[2];   // (B, 64, 4)
    const float* mus = (const float*)d_in[3];   // (B, E)
    const float* lvs = (const float*)d_in[4];   // (B, E)

    int B = in_sizes[1] / 455;                  // (K+1)*7 = 455
    if (B > 8192) B = 8192;
    int E = in_sizes[3] / B;

    int blocks = (B + 15) / 16;                 // 16 batches per 128-thread block
    phmm_fused_kernel<<<blocks, 128>>>(x, a, e, mus, lvs, (float*)d_out, B, E);
}